// round 14
// baseline (speedup 1.0000x reference)
#include <cuda_runtime.h>
#include <cuda_fp16.h>
#include <math.h>
#include <stdint.h>

#define B_  4
#define S_  1024
#define H_  16
#define DH_ 128
#define DM_ 2048
#define SKV 2048

// ---------------- scratch (device globals) ----------------
__device__ __half g_x16[B_ * S_ * DM_];
__device__ __half g_wqkvT[3 * DM_ * DM_];
__device__ __half g_woT[DM_ * DM_];
__device__ __half g_q16[B_ * H_ * S_ * DH_];
__device__ __half g_k16[B_ * H_ * SKV * DH_];
__device__ __half g_vT16[B_ * H_ * DH_ * SKV];
__device__ __half g_attn16[B_ * S_ * DM_];
__device__ float  g_cos_tab[S_ * 64];
__device__ float  g_sin_tab[S_ * 64];

// ---------------- helpers ----------------
__device__ __forceinline__ void mma_f16(float* c, const unsigned* a, unsigned b0, unsigned b1) {
    asm volatile(
        "mma.sync.aligned.m16n8k16.row.col.f32.f16.f16.f32 "
        "{%0,%1,%2,%3}, {%4,%5,%6,%7}, {%8,%9}, {%0,%1,%2,%3};\n"
        : "+f"(c[0]), "+f"(c[1]), "+f"(c[2]), "+f"(c[3])
        : "r"(a[0]), "r"(a[1]), "r"(a[2]), "r"(a[3]), "r"(b0), "r"(b1));
}

__device__ __forceinline__ void ldsm_x4(unsigned& r0, unsigned& r1, unsigned& r2, unsigned& r3,
                                        uint32_t addr) {
    asm volatile("ldmatrix.sync.aligned.m8n8.x4.shared.b16 {%0,%1,%2,%3}, [%4];"
                 : "=r"(r0), "=r"(r1), "=r"(r2), "=r"(r3) : "r"(addr));
}

__device__ __forceinline__ void cp_async16s(uint32_t smem_dst, const void* gmem_src) {
    asm volatile("cp.async.cg.shared.global [%0], [%1], 16;\n" :: "r"(smem_dst), "l"(gmem_src));
}
__device__ __forceinline__ void cp_commit() { asm volatile("cp.async.commit_group;\n" ::); }

__device__ __forceinline__ unsigned pack_h2(float a, float b) {
    __half2 h = __floats2half2_rn(a, b);
    return *reinterpret_cast<unsigned*>(&h);
}

// ---------------- prepass 1: both weight transposes ----------------
__global__ void prep_weights(const float* __restrict__ wqkv, const float* __restrict__ wo) {
    __shared__ float tile[32][33];
    int k0 = blockIdx.x * 32;
    int y = blockIdx.y;
    const float* src;
    __half* dst;
    int N;
    if (y < 192) { src = wqkv; dst = g_wqkvT; N = 6144; }
    else         { src = wo;   dst = g_woT;   N = 2048; y -= 192; }
    int n0 = y * 32;
    int tx = threadIdx.x, ty = threadIdx.y;
    #pragma unroll
    for (int i = 0; i < 4; i++) {
        int kl = ty + 8 * i;
        tile[kl][tx] = src[(size_t)(k0 + kl) * N + n0 + tx];
    }
    __syncthreads();
    #pragma unroll
    for (int i = 0; i < 4; i++) {
        int nl = ty + 8 * i;
        dst[(size_t)(n0 + nl) * 2048 + k0 + tx] = __float2half_rn(tile[tx][nl]);
    }
}

// ---------------- prepass 2: cache prep + x convert + rope table ----------------
__global__ void prep_misc(const float* __restrict__ ck, const float* __restrict__ cv,
                          const float* __restrict__ x) {
    __shared__ float tile[32][33];
    int bid = blockIdx.x;
    int tid = threadIdx.x;
    int tx = tid & 31, ty = tid >> 5;

    if (bid < 8192) {
        int bh = bid >> 7;
        int rem = bid & 127;
        int d0 = (rem >> 5) << 5;
        int s0 = (rem & 31) << 5;
        #pragma unroll
        for (int i = 0; i < 4; i++) {
            int sl = ty + 8 * i;
            g_k16[((size_t)bh * SKV + s0 + sl) * DH_ + d0 + tx] =
                __float2half_rn(ck[((size_t)bh * S_ + s0 + sl) * DH_ + d0 + tx]);
        }
        #pragma unroll
        for (int i = 0; i < 4; i++) {
            int sl = ty + 8 * i;
            tile[sl][tx] = cv[((size_t)bh * S_ + s0 + sl) * DH_ + d0 + tx];
        }
        __syncthreads();
        #pragma unroll
        for (int i = 0; i < 4; i++) {
            int dl = ty + 8 * i;
            g_vT16[((size_t)bh * DH_ + d0 + dl) * SKV + s0 + tx] =
                __float2half_rn(tile[tx][dl]);
        }
    } else if (bid < 16384) {
        int i = (bid - 8192) * 256 + tid;
        float4 v = ((const float4*)x)[i];
        __half2 h0 = __floats2half2_rn(v.x, v.y);
        __half2 h1 = __floats2half2_rn(v.z, v.w);
        ((uint2*)g_x16)[i] = make_uint2(*(unsigned*)&h0, *(unsigned*)&h1);
    } else {
        int i = (bid - 16384) * 256 + tid;
        int d = i & 63;
        int s = i >> 6;
        float inv_freq = (float)pow(10000.0, -(double)d / 64.0);
        float ang = (float)(1024 + s) * inv_freq;
        double a = (double)ang;
        g_cos_tab[i] = (float)cos(a);
        g_sin_tab[i] = (float)sin(a);
    }
}

// ---------------- fp16 GEMM (128x128 CTA, 32x64 warp, 3-stage, 2 CTAs/SM) ------
#define GST 144
#define G_TILE_BYTES (128 * GST)
#define G_STAGE_BYTES (2 * G_TILE_BYTES)
#define G_SMEM_TOTAL (3 * G_STAGE_BYTES)

template <int MODE>
__global__ void __launch_bounds__(256, 2) gemm_f16(
    const __half* __restrict__ A, const __half* __restrict__ B, float* __restrict__ C,
    int M, int N, int K)
{
    extern __shared__ __align__(16) char smc[];
    const uint32_t smb = (uint32_t)__cvta_generic_to_shared(smc);

    const int tid  = threadIdx.x;
    const int warp = tid >> 5, lane = tid & 31;
    const int g    = lane >> 2, tig = lane & 3;
    const int lr   = lane & 7, sel = lane >> 3;
    const int wm   = (warp & 3) * 32;
    const int wn   = (warp >> 2) * 64;
    const int mbase = blockIdx.y * 128;
    const int nbase = blockIdx.x * 128;
    const int KT = K >> 6;

    const int rowA = (sel & 1) * 8 + lr;
    const int koffA = (sel >> 1) * 16;
    const int rowB = (sel >> 1) * 8 + lr;
    const int koffB = (sel & 1) * 16;

    float acc[2][8][4];
    #pragma unroll
    for (int mi = 0; mi < 2; mi++)
        #pragma unroll
        for (int ni = 0; ni < 8; ni++)
            #pragma unroll
            for (int r = 0; r < 4; r++) acc[mi][ni][r] = 0.f;

    const int crow = tid >> 3, cch = tid & 7;

    auto issue = [&](int kt) {
        uint32_t As = smb + (kt % 3) * G_STAGE_BYTES;
        uint32_t Bs = As + G_TILE_BYTES;
        int k0 = kt << 6;
        #pragma unroll
        for (int i = 0; i < 4; i++) {
            int row = i * 32 + crow;
            cp_async16s(As + row * GST + cch * 16, &A[(size_t)(mbase + row) * K + k0 + cch * 8]);
            cp_async16s(Bs + row * GST + cch * 16, &B[(size_t)(nbase + row) * K + k0 + cch * 8]);
        }
        cp_commit();
    };

    issue(0);
    issue(1);

    for (int kt = 0; kt < KT; kt++) {
        if (kt + 1 < KT) { asm volatile("cp.async.wait_group 1;\n" ::); }
        else             { asm volatile("cp.async.wait_group 0;\n" ::); }
        __syncthreads();
        if (kt + 2 < KT) issue(kt + 2);

        uint32_t At = smb + (kt % 3) * G_STAGE_BYTES;
        uint32_t Bt = At + G_TILE_BYTES;
        uint32_t aAddr = At + (wm + rowA) * GST + koffA;
        uint32_t bAddr = Bt + (wn + rowB) * GST + koffB;

        #pragma unroll
        for (int kk = 0; kk < 4; kk++) {
            unsigned a[2][4], bf[8][2];
            #pragma unroll
            for (int mi = 0; mi < 2; mi++)
                ldsm_x4(a[mi][0], a[mi][1], a[mi][2], a[mi][3],
                        aAddr + mi * (16 * GST) + kk * 32);
            #pragma unroll
            for (int ni2 = 0; ni2 < 4; ni2++)
                ldsm_x4(bf[2 * ni2][0], bf[2 * ni2][1], bf[2 * ni2 + 1][0], bf[2 * ni2 + 1][1],
                        bAddr + ni2 * (16 * GST) + kk * 32);
            #pragma unroll
            for (int mi = 0; mi < 2; mi++)
                #pragma unroll
                for (int ni = 0; ni < 8; ni++)
                    mma_f16(acc[mi][ni], a[mi], bf[ni][0], bf[ni][1]);
        }
    }

    if (MODE == 0) {
        #pragma unroll
        for (int mi = 0; mi < 2; mi++) {
            #pragma unroll
            for (int ni = 0; ni < 8; ni++) {
                int r0 = mbase + wm + mi * 16 + g;
                int cc = nbase + wn + ni * 8 + tig * 2;
                *(float2*)&C[(size_t)r0 * N + cc]       = make_float2(acc[mi][ni][0], acc[mi][ni][1]);
                *(float2*)&C[(size_t)(r0 + 8) * N + cc] = make_float2(acc[mi][ni][2], acc[mi][ni][3]);
            }
        }
    } else {
        __syncthreads();
        float* Ts = (float*)smc;
        #pragma unroll
        for (int mi = 0; mi < 2; mi++) {
            #pragma unroll
            for (int ni = 0; ni < 8; ni++) {
                int r0 = wm + mi * 16 + g;
                int cc = wn + ni * 8 + tig * 2;
                Ts[r0 * 129 + cc]           = acc[mi][ni][0];
                Ts[r0 * 129 + cc + 1]       = acc[mi][ni][1];
                Ts[(r0 + 8) * 129 + cc]     = acc[mi][ni][2];
                Ts[(r0 + 8) * 129 + cc + 1] = acc[mi][ni][3];
            }
        }
        __syncthreads();

        const int h = nbase / 384;
        const int t = (nbase % 384) >> 7;
        const int b = mbase >> 10;
        const int s0 = mbase & 1023;
        const int bh = b * H_ + h;

        if (t == 2) {
            __half* dst = g_vT16 + (size_t)bh * DH_ * SKV + 1024 + s0;
            for (int idx = tid; idx < 128 * 128; idx += 256) {
                int d = idx >> 7, sl = idx & 127;
                dst[(size_t)d * SKV + sl] = __float2half_rn(Ts[sl * 129 + d]);
            }
        } else {
            const float scale = (t == 0) ? 0.08838834764831845f : 1.0f;
            for (int idx = tid; idx < 128 * 64; idx += 256) {
                int r = idx >> 6, d = idx & 63;
                int s = s0 + r;
                float v1 = Ts[r * 129 + d], v2 = Ts[r * 129 + d + 64];
                float cs = g_cos_tab[s * 64 + d], sn = g_sin_tab[s * 64 + d];
                float o1 = (v1 * cs - v2 * sn) * scale;
                float o2 = (v2 * cs + v1 * sn) * scale;
                if (t == 0) {
                    size_t oq = ((size_t)bh * S_ + s) * DH_;
                    g_q16[oq + d]      = __float2half_rn(o1);
                    g_q16[oq + 64 + d] = __float2half_rn(o2);
                } else {
                    size_t ok = ((size_t)bh * SKV + 1024 + s) * DH_;
                    g_k16[ok + d]      = __float2half_rn(o1);
                    g_k16[ok + 64 + d] = __float2half_rn(o2);
                }
            }
        }
    }
}

// ---------------- flash attention (full 2048 keys, 64-key tiles, 2 CTAs/SM) ----
#define KST 272
#define VST 144
#define Q_BYTES   (128 * KST)
#define K_TILEB   (64 * KST)
#define V_TILEB   (128 * VST)
#define ATTN_SMEM_BYTES (Q_BYTES + 2 * K_TILEB + 2 * V_TILEB)   // 106496

__global__ void __launch_bounds__(256, 2) attn_kernel() {
    extern __shared__ __align__(16) char smc[];
    const uint32_t smb = (uint32_t)__cvta_generic_to_shared(smc);
    const uint32_t Qb = smb;
    const uint32_t Kb = smb + Q_BYTES;
    const uint32_t Vb = Kb + 2 * K_TILEB;

    const int tid  = threadIdx.x;
    const int warp = tid >> 5, lane = tid & 31;
    const int g    = lane >> 2, tig = lane & 3;
    const int lr   = lane & 7, sel = lane >> 3;
    const int qt = blockIdx.x, h = blockIdx.y, b = blockIdx.z;
    const int qr = warp * 16;
    const int bh = b * H_ + h;

    const int rowA = (sel & 1) * 8 + lr;
    const int koffA = (sel >> 1) * 16;
    const int rowB = (sel >> 1) * 8 + lr;
    const int koffB = (sel & 1) * 16;

    const __half* __restrict__ Qg = g_q16 + (size_t)bh * S_ * DH_ + (size_t)qt * 128 * DH_;
    const __half* __restrict__ Kg = g_k16 + (size_t)bh * SKV * DH_;
    const __half* __restrict__ Vg = g_vT16 + (size_t)bh * DH_ * SKV;

    // load Q tile to smem
    {
        int r = tid >> 4, c = tid & 15;
        #pragma unroll
        for (int i = 0; i < 8; i++) {
            int row = i * 16 + r;
            cp_async16s(Qb + row * KST + c * 16, &Qg[(size_t)row * DH_ + c * 8]);
        }
        cp_commit();
    }

    auto issue = [&](int kt) {
        uint32_t Kd = Kb + (kt & 1) * K_TILEB;
        uint32_t Vd = Vb + (kt & 1) * V_TILEB;
        int r = tid >> 4, c = tid & 15;
        #pragma unroll
        for (int i = 0; i < 4; i++) {
            int row = i * 16 + r;
            cp_async16s(Kd + row * KST + c * 16, &Kg[(size_t)(kt * 64 + row) * DH_ + c * 8]);
        }
        int vr = tid >> 3, vc = tid & 7;
        #pragma unroll
        for (int i = 0; i < 4; i++) {
            int row = i * 32 + vr;
            cp_async16s(Vd + row * VST + vc * 16, &Vg[(size_t)row * SKV + kt * 64 + vc * 8]);
        }
        cp_commit();
    };

    issue(0);

    float o[16][4];
    #pragma unroll
    for (int ni = 0; ni < 16; ni++)
        #pragma unroll
        for (int r = 0; r < 4; r++) o[ni][r] = 0.f;
    float l0 = 0.f, l1 = 0.f;

    const uint32_t qAddr = Qb + (qr + rowA) * KST + koffA;

    for (int kt = 0; kt < 32; kt++) {
        asm volatile("cp.async.wait_group 0;\n" ::);
        __syncthreads();
        if (kt + 1 < 32) issue(kt + 1);

        uint32_t Kt = Kb + (kt & 1) * K_TILEB + rowB * KST + koffB;
        uint32_t Vt = Vb + (kt & 1) * V_TILEB + rowB * VST + koffB;

        // S[16x64] = Q @ K^T
        float s[8][4];
        #pragma unroll
        for (int ni = 0; ni < 8; ni++)
            #pragma unroll
            for (int r = 0; r < 4; r++) s[ni][r] = 0.f;

        #pragma unroll
        for (int kk = 0; kk < 8; kk++) {
            unsigned a[4];
            ldsm_x4(a[0], a[1], a[2], a[3], qAddr + kk * 32);
            #pragma unroll
            for (int ni2 = 0; ni2 < 4; ni2++) {
                unsigned b0, b1, b2, b3;
                ldsm_x4(b0, b1, b2, b3, Kt + ni2 * (16 * KST) + kk * 32);
                mma_f16(s[2 * ni2],     a, b0, b1);
                mma_f16(s[2 * ni2 + 1], a, b2, b3);
            }
        }

        // no-max softmax
        float rs0 = 0.f, rs1 = 0.f;
        #pragma unroll
        for (int ni = 0; ni < 8; ni++) {
            s[ni][0] = __expf(s[ni][0]);
            s[ni][1] = __expf(s[ni][1]);
            s[ni][2] = __expf(s[ni][2]);
            s[ni][3] = __expf(s[ni][3]);
            rs0 += s[ni][0] + s[ni][1];
            rs1 += s[ni][2] + s[ni][3];
        }
        l0 += rs0;
        l1 += rs1;

        // O += P @ V
        #pragma unroll
        for (int j = 0; j < 4; j++) {
            unsigned ap[4];
            ap[0] = pack_h2(s[2 * j][0],     s[2 * j][1]);
            ap[1] = pack_h2(s[2 * j][2],     s[2 * j][3]);
            ap[2] = pack_h2(s[2 * j + 1][0], s[2 * j + 1][1]);
            ap[3] = pack_h2(s[2 * j + 1][2], s[2 * j + 1][3]);
            #pragma unroll
            for (int ni2 = 0; ni2 < 8; ni2++) {
                unsigned b0, b1, b2, b3;
                ldsm_x4(b0, b1, b2, b3, Vt + ni2 * (16 * VST) + j * 32);
                mma_f16(o[2 * ni2],     ap, b0, b1);
                mma_f16(o[2 * ni2 + 1], ap, b2, b3);
            }
        }
    }

    l0 += __shfl_xor_sync(0xffffffffu, l0, 1);
    l0 += __shfl_xor_sync(0xffffffffu, l0, 2);
    l1 += __shfl_xor_sync(0xffffffffu, l1, 1);
    l1 += __shfl_xor_sync(0xffffffffu, l1, 2);

    // epilogue: normalize, write fp16 [B,S,H*D] directly
    float inv0 = 1.f / l0, inv1 = 1.f / l1;
    int srow = qt * 128 + qr;
    __half* Og = g_attn16 + (size_t)(b * S_ + srow) * DM_ + h * DH_;
    #pragma unroll
    for (int ni = 0; ni < 16; ni++) {
        int col = ni * 8 + tig * 2;
        *(unsigned*)&Og[(size_t)g * DM_ + col]       = pack_h2(o[ni][0] * inv0, o[ni][1] * inv0);
        *(unsigned*)&Og[(size_t)(g + 8) * DM_ + col] = pack_h2(o[ni][2] * inv1, o[ni][3] * inv1);
    }
}

// ---------------- launch ----------------
extern "C" void kernel_launch(void* const* d_in, const int* in_sizes, int n_in,
                              void* d_out, int out_size) {
    const float* x       = (const float*)d_in[0];
    const float* cache_k = (const float*)d_in[1];
    const float* cache_v = (const float*)d_in[2];
    const float* w_qkv   = (const float*)d_in[3];
    const float* w_o     = (const float*)d_in[4];
    float* out = (float*)d_out;

    __half *px16, *pwqkvT, *pwoT, *pattn16;
    cudaGetSymbolAddress((void**)&px16,    g_x16);
    cudaGetSymbolAddress((void**)&pwqkvT,  g_wqkvT);
    cudaGetSymbolAddress((void**)&pwoT,    g_woT);
    cudaGetSymbolAddress((void**)&pattn16, g_attn16);

    cudaFuncSetAttribute(gemm_f16<0>, cudaFuncAttributeMaxDynamicSharedMemorySize, G_SMEM_TOTAL);
    cudaFuncSetAttribute(gemm_f16<1>, cudaFuncAttributeMaxDynamicSharedMemorySize, G_SMEM_TOTAL);
    cudaFuncSetAttribute(attn_kernel, cudaFuncAttributeMaxDynamicSharedMemorySize, ATTN_SMEM_BYTES);

    // launch order: attn is my #4 == global #6 -> profiled by ncu -s 5 -c 1
    prep_weights<<<dim3(64, 256), dim3(32, 8)>>>(w_qkv, w_o);                 // 1
    prep_misc<<<16640, 256>>>(cache_k, cache_v, x);                           // 2
    gemm_f16<1><<<dim3((3 * DM_) / 128, (B_ * S_) / 128), 256, G_SMEM_TOTAL>>>(
        px16, pwqkvT, nullptr, B_ * S_, 3 * DM_, DM_);                        // 3
    attn_kernel<<<dim3(S_ / 128, H_, B_), 256, ATTN_SMEM_BYTES>>>();          // 4
    gemm_f16<0><<<dim3(DM_ / 128, (B_ * S_) / 128), 256, G_SMEM_TOTAL>>>(
        pattn16, pwoT, out, B_ * S_, DM_, DM_);                               // 5
}

// round 15
// speedup vs baseline: 1.0257x; 1.0257x over previous
#include <cuda_runtime.h>
#include <cuda_fp16.h>
#include <math.h>
#include <stdint.h>

#define B_  4
#define S_  1024
#define H_  16
#define DH_ 128
#define DM_ 2048
#define SKV 2048
#define NSPLIT 2

// ---------------- scratch (device globals) ----------------
__device__ __half g_x16[B_ * S_ * DM_];
__device__ __half g_wqkvT[3 * DM_ * DM_];
__device__ __half g_woT[DM_ * DM_];
__device__ __half g_q16[B_ * H_ * S_ * DH_];    // rope'd, scaled by log2e/sqrt(d)
__device__ __half g_k16[B_ * H_ * SKV * DH_];
__device__ __half g_vT16[B_ * H_ * DH_ * SKV];
__device__ __half g_attn16[B_ * S_ * DM_];
__device__ __half g_opart16[NSPLIT * B_ * S_ * DM_];
__device__ float  g_lpart[NSPLIT * B_ * H_ * S_];
__device__ float  g_cos_tab[S_ * 64];
__device__ float  g_sin_tab[S_ * 64];

// ---------------- helpers ----------------
__device__ __forceinline__ void mma_f16(float* c, const unsigned* a, unsigned b0, unsigned b1) {
    asm volatile(
        "mma.sync.aligned.m16n8k16.row.col.f32.f16.f16.f32 "
        "{%0,%1,%2,%3}, {%4,%5,%6,%7}, {%8,%9}, {%0,%1,%2,%3};\n"
        : "+f"(c[0]), "+f"(c[1]), "+f"(c[2]), "+f"(c[3])
        : "r"(a[0]), "r"(a[1]), "r"(a[2]), "r"(a[3]), "r"(b0), "r"(b1));
}

__device__ __forceinline__ void ldsm_x4(unsigned& r0, unsigned& r1, unsigned& r2, unsigned& r3,
                                        uint32_t addr) {
    asm volatile("ldmatrix.sync.aligned.m8n8.x4.shared.b16 {%0,%1,%2,%3}, [%4];"
                 : "=r"(r0), "=r"(r1), "=r"(r2), "=r"(r3) : "r"(addr));
}

__device__ __forceinline__ void cp_async16s(uint32_t smem_dst, const void* gmem_src) {
    asm volatile("cp.async.cg.shared.global [%0], [%1], 16;\n" :: "r"(smem_dst), "l"(gmem_src));
}
__device__ __forceinline__ void cp_commit() { asm volatile("cp.async.commit_group;\n" ::); }

__device__ __forceinline__ unsigned pack_h2(float a, float b) {
    __half2 h = __floats2half2_rn(a, b);
    return *reinterpret_cast<unsigned*>(&h);
}

// ---------------- prepass 1: both weight transposes ----------------
__global__ void prep_weights(const float* __restrict__ wqkv, const float* __restrict__ wo) {
    __shared__ float tile[32][33];
    int k0 = blockIdx.x * 32;
    int y = blockIdx.y;
    const float* src;
    __half* dst;
    int N;
    if (y < 192) { src = wqkv; dst = g_wqkvT; N = 6144; }
    else         { src = wo;   dst = g_woT;   N = 2048; y -= 192; }
    int n0 = y * 32;
    int tx = threadIdx.x, ty = threadIdx.y;
    #pragma unroll
    for (int i = 0; i < 4; i++) {
        int kl = ty + 8 * i;
        tile[kl][tx] = src[(size_t)(k0 + kl) * N + n0 + tx];
    }
    __syncthreads();
    #pragma unroll
    for (int i = 0; i < 4; i++) {
        int nl = ty + 8 * i;
        dst[(size_t)(n0 + nl) * 2048 + k0 + tx] = __float2half_rn(tile[tx][nl]);
    }
}

// ---------------- prepass 2: cache k copy (vectorized) + v transpose ----------
__global__ void prep_cache(const float* __restrict__ ck, const float* __restrict__ cv) {
    __shared__ float tile[32][33];
    int bid = blockIdx.x;
    int tid = threadIdx.x;
    int bh = bid >> 7;
    int rem = bid & 127;
    int d0 = (rem >> 5) << 5;
    int s0 = (rem & 31) << 5;
    int tx = tid & 31, ty = tid >> 5;

    // K: convert-copy, 4 floats -> uint2 per thread (8 threads cover 32 d)
    {
        int dt = (tid & 7) * 4;           // d offset within 32
        int sl = tid >> 3;                // 32 rows
        const float4 v = *(const float4*)&ck[((size_t)bh * S_ + s0 + sl) * DH_ + d0 + dt];
        __half2 h0 = __floats2half2_rn(v.x, v.y);
        __half2 h1 = __floats2half2_rn(v.z, v.w);
        *(uint2*)&g_k16[((size_t)bh * SKV + s0 + sl) * DH_ + d0 + dt] =
            make_uint2(*(unsigned*)&h0, *(unsigned*)&h1);
    }
    // V: transpose via smem
    #pragma unroll
    for (int i = 0; i < 4; i++) {
        int sl = ty + 8 * i;
        tile[sl][tx] = cv[((size_t)bh * S_ + s0 + sl) * DH_ + d0 + tx];
    }
    __syncthreads();
    #pragma unroll
    for (int i = 0; i < 4; i++) {
        int dl = ty + 8 * i;
        g_vT16[((size_t)bh * DH_ + d0 + dl) * SKV + s0 + tx] =
            __float2half_rn(tile[tx][dl]);
    }
}

// ---------------- prepass 3: x convert + rope table ----------------
__global__ void prep_xrope(const float* __restrict__ x) {
    int bid = blockIdx.x;
    int tid = threadIdx.x;
    if (bid < 8192) {
        int i = bid * 256 + tid;
        float4 v = ((const float4*)x)[i];
        __half2 h0 = __floats2half2_rn(v.x, v.y);
        __half2 h1 = __floats2half2_rn(v.z, v.w);
        ((uint2*)g_x16)[i] = make_uint2(*(unsigned*)&h0, *(unsigned*)&h1);
    } else {
        int i = (bid - 8192) * 256 + tid;
        int d = i & 63;
        int s = i >> 6;
        float inv_freq = (float)pow(10000.0, -(double)d / 64.0);
        float ang = (float)(1024 + s) * inv_freq;
        double a = (double)ang;
        g_cos_tab[i] = (float)cos(a);
        g_sin_tab[i] = (float)sin(a);
    }
}

// ---------------- fp16 GEMM (128x128 CTA, 32x64 warp, 3-stage, 2 CTAs/SM) ------
#define GST 144
#define G_TILE_BYTES (128 * GST)
#define G_STAGE_BYTES (2 * G_TILE_BYTES)
#define G_SMEM_TOTAL (3 * G_STAGE_BYTES)

template <int MODE>
__global__ void __launch_bounds__(256, 2) gemm_f16(
    const __half* __restrict__ A, const __half* __restrict__ B, float* __restrict__ C,
    int M, int N, int K)
{
    extern __shared__ __align__(16) char smc[];
    const uint32_t smb = (uint32_t)__cvta_generic_to_shared(smc);

    const int tid  = threadIdx.x;
    const int warp = tid >> 5, lane = tid & 31;
    const int g    = lane >> 2, tig = lane & 3;
    const int lr   = lane & 7, sel = lane >> 3;
    const int wm   = (warp & 3) * 32;
    const int wn   = (warp >> 2) * 64;
    const int mbase = blockIdx.y * 128;
    const int nbase = blockIdx.x * 128;
    const int KT = K >> 6;

    const int rowA = (sel & 1) * 8 + lr;
    const int koffA = (sel >> 1) * 16;
    const int rowB = (sel >> 1) * 8 + lr;
    const int koffB = (sel & 1) * 16;

    float acc[2][8][4];
    #pragma unroll
    for (int mi = 0; mi < 2; mi++)
        #pragma unroll
        for (int ni = 0; ni < 8; ni++)
            #pragma unroll
            for (int r = 0; r < 4; r++) acc[mi][ni][r] = 0.f;

    const int crow = tid >> 3, cch = tid & 7;

    auto issue = [&](int kt) {
        uint32_t As = smb + (kt % 3) * G_STAGE_BYTES;
        uint32_t Bs = As + G_TILE_BYTES;
        int k0 = kt << 6;
        #pragma unroll
        for (int i = 0; i < 4; i++) {
            int row = i * 32 + crow;
            cp_async16s(As + row * GST + cch * 16, &A[(size_t)(mbase + row) * K + k0 + cch * 8]);
            cp_async16s(Bs + row * GST + cch * 16, &B[(size_t)(nbase + row) * K + k0 + cch * 8]);
        }
        cp_commit();
    };

    issue(0);
    issue(1);

    for (int kt = 0; kt < KT; kt++) {
        if (kt + 1 < KT) { asm volatile("cp.async.wait_group 1;\n" ::); }
        else             { asm volatile("cp.async.wait_group 0;\n" ::); }
        __syncthreads();
        if (kt + 2 < KT) issue(kt + 2);

        uint32_t At = smb + (kt % 3) * G_STAGE_BYTES;
        uint32_t Bt = At + G_TILE_BYTES;
        uint32_t aAddr = At + (wm + rowA) * GST + koffA;
        uint32_t bAddr = Bt + (wn + rowB) * GST + koffB;

        #pragma unroll
        for (int kk = 0; kk < 4; kk++) {
            unsigned a[2][4], bf[8][2];
            #pragma unroll
            for (int mi = 0; mi < 2; mi++)
                ldsm_x4(a[mi][0], a[mi][1], a[mi][2], a[mi][3],
                        aAddr + mi * (16 * GST) + kk * 32);
            #pragma unroll
            for (int ni2 = 0; ni2 < 4; ni2++)
                ldsm_x4(bf[2 * ni2][0], bf[2 * ni2][1], bf[2 * ni2 + 1][0], bf[2 * ni2 + 1][1],
                        bAddr + ni2 * (16 * GST) + kk * 32);
            #pragma unroll
            for (int mi = 0; mi < 2; mi++)
                #pragma unroll
                for (int ni = 0; ni < 8; ni++)
                    mma_f16(acc[mi][ni], a[mi], bf[ni][0], bf[ni][1]);
        }
    }

    if (MODE == 0) {
        #pragma unroll
        for (int mi = 0; mi < 2; mi++) {
            #pragma unroll
            for (int ni = 0; ni < 8; ni++) {
                int r0 = mbase + wm + mi * 16 + g;
                int cc = nbase + wn + ni * 8 + tig * 2;
                *(float2*)&C[(size_t)r0 * N + cc]       = make_float2(acc[mi][ni][0], acc[mi][ni][1]);
                *(float2*)&C[(size_t)(r0 + 8) * N + cc] = make_float2(acc[mi][ni][2], acc[mi][ni][3]);
            }
        }
    } else {
        __syncthreads();
        float* Ts = (float*)smc;
        #pragma unroll
        for (int mi = 0; mi < 2; mi++) {
            #pragma unroll
            for (int ni = 0; ni < 8; ni++) {
                int r0 = wm + mi * 16 + g;
                int cc = wn + ni * 8 + tig * 2;
                Ts[r0 * 129 + cc]           = acc[mi][ni][0];
                Ts[r0 * 129 + cc + 1]       = acc[mi][ni][1];
                Ts[(r0 + 8) * 129 + cc]     = acc[mi][ni][2];
                Ts[(r0 + 8) * 129 + cc + 1] = acc[mi][ni][3];
            }
        }
        __syncthreads();

        const int h = nbase / 384;
        const int t = (nbase % 384) >> 7;
        const int b = mbase >> 10;
        const int s0 = mbase & 1023;
        const int bh = b * H_ + h;

        if (t == 2) {
            __half* dst = g_vT16 + (size_t)bh * DH_ * SKV + 1024 + s0;
            for (int idx = tid; idx < 128 * 128; idx += 256) {
                int d = idx >> 7, sl = idx & 127;
                dst[(size_t)d * SKV + sl] = __float2half_rn(Ts[sl * 129 + d]);
            }
        } else {
            // q scale folds in log2(e) so attention can use exp2f
            const float scale = (t == 0) ? 0.1275174056180437f : 1.0f;  // log2e/sqrt(128)
            for (int idx = tid; idx < 128 * 64; idx += 256) {
                int r = idx >> 6, d = idx & 63;
                int s = s0 + r;
                float v1 = Ts[r * 129 + d], v2 = Ts[r * 129 + d + 64];
                float cs = g_cos_tab[s * 64 + d], sn = g_sin_tab[s * 64 + d];
                float o1 = (v1 * cs - v2 * sn) * scale;
                float o2 = (v2 * cs + v1 * sn) * scale;
                if (t == 0) {
                    size_t oq = ((size_t)bh * S_ + s) * DH_;
                    g_q16[oq + d]      = __float2half_rn(o1);
                    g_q16[oq + 64 + d] = __float2half_rn(o2);
                } else {
                    size_t ok = ((size_t)bh * SKV + 1024 + s) * DH_;
                    g_k16[ok + d]      = __float2half_rn(o1);
                    g_k16[ok + 64 + d] = __float2half_rn(o2);
                }
            }
        }
    }
}

// ---------------- flash attention (split-KV=2, 64-key tiles, 2 CTAs/SM) --------
#define KST 272
#define VST 144
#define Q_BYTES   (128 * KST)
#define K_TILEB   (64 * KST)
#define V_TILEB   (128 * VST)
#define ATTN_SMEM_BYTES (Q_BYTES + 2 * K_TILEB + 2 * V_TILEB)   // 106496

__global__ void __launch_bounds__(256, 2) attn_kernel() {
    extern __shared__ __align__(16) char smc[];
    const uint32_t smb = (uint32_t)__cvta_generic_to_shared(smc);
    const uint32_t Qb = smb;
    const uint32_t Kb = smb + Q_BYTES;
    const uint32_t Vb = Kb + 2 * K_TILEB;

    const int tid  = threadIdx.x;
    const int warp = tid >> 5, lane = tid & 31;
    const int g    = lane >> 2, tig = lane & 3;
    const int lr   = lane & 7, sel = lane >> 3;
    const int qt = blockIdx.x, h = blockIdx.y;
    const int b = blockIdx.z >> 1, half = blockIdx.z & 1;
    const int qr = warp * 16;
    const int bh = b * H_ + h;

    const int rowA = (sel & 1) * 8 + lr;
    const int koffA = (sel >> 1) * 16;
    const int rowB = (sel >> 1) * 8 + lr;
    const int koffB = (sel & 1) * 16;

    const __half* __restrict__ Qg = g_q16 + (size_t)bh * S_ * DH_ + (size_t)qt * 128 * DH_;
    const __half* __restrict__ Kg = g_k16 + (size_t)bh * SKV * DH_;
    const __half* __restrict__ Vg = g_vT16 + (size_t)bh * DH_ * SKV;

    {
        int r = tid >> 4, c = tid & 15;
        #pragma unroll
        for (int i = 0; i < 8; i++) {
            int row = i * 16 + r;
            cp_async16s(Qb + row * KST + c * 16, &Qg[(size_t)row * DH_ + c * 8]);
        }
        cp_commit();
    }

    auto issue = [&](int kt) {
        uint32_t Kd = Kb + (kt & 1) * K_TILEB;
        uint32_t Vd = Vb + (kt & 1) * V_TILEB;
        int r = tid >> 4, c = tid & 15;
        #pragma unroll
        for (int i = 0; i < 4; i++) {
            int row = i * 16 + r;
            cp_async16s(Kd + row * KST + c * 16, &Kg[(size_t)(kt * 64 + row) * DH_ + c * 8]);
        }
        int vr = tid >> 3, vc = tid & 7;
        #pragma unroll
        for (int i = 0; i < 4; i++) {
            int row = i * 32 + vr;
            cp_async16s(Vd + row * VST + vc * 16, &Vg[(size_t)row * SKV + kt * 64 + vc * 8]);
        }
        cp_commit();
    };

    const int kt0 = half * 16, kt1 = kt0 + 16;
    issue(kt0);

    float o[16][4];
    #pragma unroll
    for (int ni = 0; ni < 16; ni++)
        #pragma unroll
        for (int r = 0; r < 4; r++) o[ni][r] = 0.f;
    float l0 = 0.f, l1 = 0.f;

    const uint32_t qAddr = Qb + (qr + rowA) * KST + koffA;

    for (int kt = kt0; kt < kt1; kt++) {
        asm volatile("cp.async.wait_group 0;\n" ::);
        __syncthreads();
        if (kt + 1 < kt1) issue(kt + 1);

        uint32_t Kt = Kb + (kt & 1) * K_TILEB + rowB * KST + koffB;
        uint32_t Vt = Vb + (kt & 1) * V_TILEB + rowB * VST + koffB;

        float s[8][4];
        #pragma unroll
        for (int ni = 0; ni < 8; ni++)
            #pragma unroll
            for (int r = 0; r < 4; r++) s[ni][r] = 0.f;

        #pragma unroll
        for (int kk = 0; kk < 8; kk++) {
            unsigned a[4];
            ldsm_x4(a[0], a[1], a[2], a[3], qAddr + kk * 32);
            #pragma unroll
            for (int ni2 = 0; ni2 < 4; ni2++) {
                unsigned b0, b1, b2, b3;
                ldsm_x4(b0, b1, b2, b3, Kt + ni2 * (16 * KST) + kk * 32);
                mma_f16(s[2 * ni2],     a, b0, b1);
                mma_f16(s[2 * ni2 + 1], a, b2, b3);
            }
        }

        // no-max softmax with exp2 (log2e pre-folded into q)
        float rs0 = 0.f, rs1 = 0.f;
        #pragma unroll
        for (int ni = 0; ni < 8; ni++) {
            s[ni][0] = exp2f(s[ni][0]);
            s[ni][1] = exp2f(s[ni][1]);
            s[ni][2] = exp2f(s[ni][2]);
            s[ni][3] = exp2f(s[ni][3]);
            rs0 += s[ni][0] + s[ni][1];
            rs1 += s[ni][2] + s[ni][3];
        }
        l0 += rs0;
        l1 += rs1;

        #pragma unroll
        for (int j = 0; j < 4; j++) {
            unsigned ap[4];
            ap[0] = pack_h2(s[2 * j][0],     s[2 * j][1]);
            ap[1] = pack_h2(s[2 * j][2],     s[2 * j][3]);
            ap[2] = pack_h2(s[2 * j + 1][0], s[2 * j + 1][1]);
            ap[3] = pack_h2(s[2 * j + 1][2], s[2 * j + 1][3]);
            #pragma unroll
            for (int ni2 = 0; ni2 < 8; ni2++) {
                unsigned b0, b1, b2, b3;
                ldsm_x4(b0, b1, b2, b3, Vt + ni2 * (16 * VST) + j * 32);
                mma_f16(o[2 * ni2],     ap, b0, b1);
                mma_f16(o[2 * ni2 + 1], ap, b2, b3);
            }
        }
    }

    l0 += __shfl_xor_sync(0xffffffffu, l0, 1);
    l0 += __shfl_xor_sync(0xffffffffu, l0, 2);
    l1 += __shfl_xor_sync(0xffffffffu, l1, 1);
    l1 += __shfl_xor_sync(0xffffffffu, l1, 2);

    int srow = qt * 128 + qr;
    __half* Op = g_opart16 + (size_t)half * (B_ * S_ * DM_)
               + ((size_t)(b * S_ + srow) * DM_ + h * DH_);
    #pragma unroll
    for (int ni = 0; ni < 16; ni++) {
        int col = ni * 8 + tig * 2;
        *(unsigned*)&Op[(size_t)g * DM_ + col]       = pack_h2(o[ni][0], o[ni][1]);
        *(unsigned*)&Op[(size_t)(g + 8) * DM_ + col] = pack_h2(o[ni][2], o[ni][3]);
    }
    if (tig == 0) {
        g_lpart[half * (B_ * H_ * S_) + bh * S_ + srow + g]     = l0;
        g_lpart[half * (B_ * H_ * S_) + bh * S_ + srow + g + 8] = l1;
    }
}

// ---------------- combine partials -> normalized fp16 attn output --------------
__global__ void combine_kernel() {
    int i = blockIdx.x * blockDim.x + threadIdx.x;
    const int n8 = B_ * S_ * DM_ / 8;
    if (i >= n8) return;
    int row = i >> 8;
    int h = ((i & 255) * 8) >> 7;
    int b = row >> 10, s = row & 1023;
    int li = (b * H_ + h) * S_ + s;

    float acc[8] = {0.f, 0.f, 0.f, 0.f, 0.f, 0.f, 0.f, 0.f};
    float l = 0.f;
    #pragma unroll
    for (int q = 0; q < NSPLIT; q++) {
        l += g_lpart[q * (B_ * H_ * S_) + li];
        uint4 v = ((const uint4*)g_opart16)[(size_t)q * n8 + i];
        const __half2* hp = (const __half2*)&v;
        #pragma unroll
        for (int j = 0; j < 4; j++) {
            float2 f = __half22float2(hp[j]);
            acc[2 * j]     += f.x;
            acc[2 * j + 1] += f.y;
        }
    }
    float inv = 1.f / l;
    uint4 outv;
    unsigned* op = (unsigned*)&outv;
    #pragma unroll
    for (int j = 0; j < 4; j++)
        op[j] = pack_h2(acc[2 * j] * inv, acc[2 * j + 1] * inv);
    ((uint4*)g_attn16)[i] = outv;
}

// ---------------- launch ----------------
extern "C" void kernel_launch(void* const* d_in, const int* in_sizes, int n_in,
                              void* d_out, int out_size) {
    const float* x       = (const float*)d_in[0];
    const float* cache_k = (const float*)d_in[1];
    const float* cache_v = (const float*)d_in[2];
    const float* w_qkv   = (const float*)d_in[3];
    const float* w_o     = (const float*)d_in[4];
    float* out = (float*)d_out;

    __half *px16, *pwqkvT, *pwoT, *pattn16;
    cudaGetSymbolAddress((void**)&px16,    g_x16);
    cudaGetSymbolAddress((void**)&pwqkvT,  g_wqkvT);
    cudaGetSymbolAddress((void**)&pwoT,    g_woT);
    cudaGetSymbolAddress((void**)&pattn16, g_attn16);

    cudaFuncSetAttribute(gemm_f16<0>, cudaFuncAttributeMaxDynamicSharedMemorySize, G_SMEM_TOTAL);
    cudaFuncSetAttribute(gemm_f16<1>, cudaFuncAttributeMaxDynamicSharedMemorySize, G_SMEM_TOTAL);
    cudaFuncSetAttribute(attn_kernel, cudaFuncAttributeMaxDynamicSharedMemorySize, ATTN_SMEM_BYTES);

    // launch order: QKV GEMM is my #4 == global #6 -> profiled by ncu -s 5 -c 1
    prep_weights<<<dim3(64, 256), dim3(32, 8)>>>(w_qkv, w_o);                 // 1
    prep_cache<<<8192, 256>>>(cache_k, cache_v);                              // 2
    prep_xrope<<<8448, 256>>>(x);                                             // 3
    gemm_f16<1><<<dim3((3 * DM_) / 128, (B_ * S_) / 128), 256, G_SMEM_TOTAL>>>(
        px16, pwqkvT, nullptr, B_ * S_, 3 * DM_, DM_);                        // 4
    attn_kernel<<<dim3(S_ / 128, H_, B_ * NSPLIT), 256, ATTN_SMEM_BYTES>>>(); // 5
    combine_kernel<<<(B_ * S_ * DM_ / 8 + 255) / 256, 256>>>();               // 6
    gemm_f16<0><<<dim3(DM_ / 128, (B_ * S_) / 128), 256, G_SMEM_TOTAL>>>(
        pattn16, pwoT, out, B_ * S_, DM_, DM_);                               // 7
}